// round 3
// baseline (speedup 1.0000x reference)
#include <cuda_runtime.h>

// Problem constants
#define NB    16
#define N_TOT 16384
#define PPT   128
#define FEAT  256
#define EMB   100
#define OUTW  200

typedef unsigned long long u64;

__device__ __forceinline__ u64 pk2(float lo, float hi) {
    u64 r; asm("mov.b64 %0, {%1,%2};" : "=l"(r) : "f"(lo), "f"(hi)); return r;
}
__device__ __forceinline__ void fma2(u64& a, u64 x, u64 w) {
    asm("fma.rn.f32x2 %0, %1, %2, %0;" : "+l"(a) : "l"(x), "l"(w));
}
__device__ __forceinline__ float2 up2(u64 v) {
    float2 f; asm("mov.b64 {%0,%1}, %2;" : "=f"(f.x), "=f"(f.y) : "l"(v)); return f;
}

// Shared-row indexing with per-8-row skew so warp-level loads (4 distinct
// mg-groups x broadcast-8) land on distinct bank quads. Rows stay 16B aligned.
#define H1I(p) ((p) * 68 + ((p) >> 3) * 4)
#define H2I(p) ((p) * 132 + ((p) >> 3) * 4)
#define H2_WORDS (128 * 132 + 16 * 4)   // 16960
#define H1_WORDS (128 * 68 + 16 * 4)    // 8768
#define DSM_BYTES ((H2_WORDS + H1_WORDS) * 4)  // 102912

// ---------------------------------------------------------------------------
// Point branch: block = one object (128 points), 128 threads.
//   h1 = relu(pts @ W1 + b1)           -> shared (128x64, skewed)
//   h2 = relu(h1 @ W2 + b2)            -> shared (128x128, skewed)
//   h3 = h2 @ W3 (swept once, 4 passes of 64 cols), max-pooled on the fly
//   feat = max + b3 ; pt_out = feat @ oe_w + oe_b
// Thread map for GEMMs: mg = t>>3 (16 groups x 8 pts), ng = t&7 (8 x 8 cols).
// Inner math uses packed fma.rn.f32x2 (o-dimension paired).
// ---------------------------------------------------------------------------
__global__ __launch_bounds__(128) void point_branch_kernel(
    const float* __restrict__ pts,   // (N_TOT, 128, 3)
    const float* __restrict__ w1,    // (3, 64)
    const float* __restrict__ b1,    // (64)
    const float* __restrict__ w2,    // (64, 128)
    const float* __restrict__ b2,    // (128)
    const float* __restrict__ w3,    // (128, 256)
    const float* __restrict__ b3,    // (256)
    const float* __restrict__ oew,   // (256, 100)
    const float* __restrict__ oeb,   // (100)
    float* __restrict__ out)         // (N_TOT, 200)
{
    extern __shared__ float dsm[];
    float* h2s = dsm;              // H2_WORDS
    float* h1s = dsm + H2_WORDS;   // H1_WORDS
    __shared__ float red[16 * 64];
    __shared__ float feat_s[256];

    const int n  = blockIdx.x;
    const int t  = threadIdx.x;
    const int mg = t >> 3;
    const int ng = t & 7;

    // ---- layer 1: thread = one point, 64 outputs (uniform weight loads)
    {
        const size_t pb = ((size_t)n * PPT + t) * 3;
        const float x = pts[pb + 0];
        const float y = pts[pb + 1];
        const float z = pts[pb + 2];
        const int hb = H1I(t);
#pragma unroll
        for (int j = 0; j < 64; j += 4) {
            float4 v;
            v.x = fmaf(x, __ldg(w1 + j + 0), fmaf(y, __ldg(w1 + 64 + j + 0), fmaf(z, __ldg(w1 + 128 + j + 0), __ldg(b1 + j + 0))));
            v.y = fmaf(x, __ldg(w1 + j + 1), fmaf(y, __ldg(w1 + 64 + j + 1), fmaf(z, __ldg(w1 + 128 + j + 1), __ldg(b1 + j + 1))));
            v.z = fmaf(x, __ldg(w1 + j + 2), fmaf(y, __ldg(w1 + 64 + j + 2), fmaf(z, __ldg(w1 + 128 + j + 2), __ldg(b1 + j + 2))));
            v.w = fmaf(x, __ldg(w1 + j + 3), fmaf(y, __ldg(w1 + 64 + j + 3), fmaf(z, __ldg(w1 + 128 + j + 3), __ldg(b1 + j + 3))));
            v.x = fmaxf(v.x, 0.0f); v.y = fmaxf(v.y, 0.0f);
            v.z = fmaxf(v.z, 0.0f); v.w = fmaxf(v.w, 0.0f);
            *(float4*)&h1s[hb + j] = v;
        }
    }
    __syncthreads();

    // ---- layer 2: h2(128x128) = relu(h1 @ W2 + b2), 2 passes of 64 cols
#pragma unroll 1
    for (int np = 0; np < 2; ++np) {
        const int c0 = np * 64 + ng * 8;
        u64 acc[8][4];
        {
            const ulonglong2 bb0 = __ldg((const ulonglong2*)(b2 + c0));
            const ulonglong2 bb1 = __ldg((const ulonglong2*)(b2 + c0 + 4));
#pragma unroll
            for (int i = 0; i < 8; ++i) {
                acc[i][0] = bb0.x; acc[i][1] = bb0.y;
                acc[i][2] = bb1.x; acc[i][3] = bb1.y;
            }
        }
#pragma unroll 1
        for (int k = 0; k < 64; k += 4) {
            float4 a[8];
#pragma unroll
            for (int i = 0; i < 8; ++i)
                a[i] = *(const float4*)&h1s[H1I(mg * 8 + i) + k];
            ulonglong2 wv0[4], wv1[4];
#pragma unroll
            for (int q = 0; q < 4; ++q) {
                const float* wr = w2 + (size_t)(k + q) * 128 + c0;
                wv0[q] = __ldg((const ulonglong2*)(wr));
                wv1[q] = __ldg((const ulonglong2*)(wr + 4));
            }
#pragma unroll
            for (int i = 0; i < 8; ++i) {
                const u64 s0 = pk2(a[i].x, a[i].x);
                fma2(acc[i][0], s0, wv0[0].x); fma2(acc[i][1], s0, wv0[0].y);
                fma2(acc[i][2], s0, wv1[0].x); fma2(acc[i][3], s0, wv1[0].y);
                const u64 s1 = pk2(a[i].y, a[i].y);
                fma2(acc[i][0], s1, wv0[1].x); fma2(acc[i][1], s1, wv0[1].y);
                fma2(acc[i][2], s1, wv1[1].x); fma2(acc[i][3], s1, wv1[1].y);
                const u64 s2 = pk2(a[i].z, a[i].z);
                fma2(acc[i][0], s2, wv0[2].x); fma2(acc[i][1], s2, wv0[2].y);
                fma2(acc[i][2], s2, wv1[2].x); fma2(acc[i][3], s2, wv1[2].y);
                const u64 s3 = pk2(a[i].w, a[i].w);
                fma2(acc[i][0], s3, wv0[3].x); fma2(acc[i][1], s3, wv0[3].y);
                fma2(acc[i][2], s3, wv1[3].x); fma2(acc[i][3], s3, wv1[3].y);
            }
        }
#pragma unroll
        for (int i = 0; i < 8; ++i) {
            const int hb = H2I(mg * 8 + i) + c0;
            const float2 p0 = up2(acc[i][0]), p1 = up2(acc[i][1]);
            const float2 p2 = up2(acc[i][2]), p3 = up2(acc[i][3]);
            float4 v0, v1;
            v0.x = fmaxf(p0.x, 0.0f); v0.y = fmaxf(p0.y, 0.0f);
            v0.z = fmaxf(p1.x, 0.0f); v0.w = fmaxf(p1.y, 0.0f);
            v1.x = fmaxf(p2.x, 0.0f); v1.y = fmaxf(p2.y, 0.0f);
            v1.z = fmaxf(p3.x, 0.0f); v1.w = fmaxf(p3.y, 0.0f);
            *(float4*)&h2s[hb]     = v0;
            *(float4*)&h2s[hb + 4] = v1;
        }
    }
    __syncthreads();

    // ---- layer 3: h3 = h2 @ W3, W3 swept ONCE (4 passes of 64 cols),
    //      max-pool over all 128 points folded into the epilogue per pass.
#pragma unroll 1
    for (int np = 0; np < 4; ++np) {
        const int c0 = np * 64 + ng * 8;
        u64 acc[8][4];
#pragma unroll
        for (int i = 0; i < 8; ++i) {
            acc[i][0] = 0ull; acc[i][1] = 0ull;
            acc[i][2] = 0ull; acc[i][3] = 0ull;
        }
#pragma unroll 1
        for (int k = 0; k < 128; k += 4) {
            float4 a[8];
#pragma unroll
            for (int i = 0; i < 8; ++i)
                a[i] = *(const float4*)&h2s[H2I(mg * 8 + i) + k];
            ulonglong2 wv0[4], wv1[4];
#pragma unroll
            for (int q = 0; q < 4; ++q) {
                const float* wr = w3 + (size_t)(k + q) * 256 + c0;
                wv0[q] = __ldg((const ulonglong2*)(wr));
                wv1[q] = __ldg((const ulonglong2*)(wr + 4));
            }
#pragma unroll
            for (int i = 0; i < 8; ++i) {
                const u64 s0 = pk2(a[i].x, a[i].x);
                fma2(acc[i][0], s0, wv0[0].x); fma2(acc[i][1], s0, wv0[0].y);
                fma2(acc[i][2], s0, wv1[0].x); fma2(acc[i][3], s0, wv1[0].y);
                const u64 s1 = pk2(a[i].y, a[i].y);
                fma2(acc[i][0], s1, wv0[1].x); fma2(acc[i][1], s1, wv0[1].y);
                fma2(acc[i][2], s1, wv1[1].x); fma2(acc[i][3], s1, wv1[1].y);
                const u64 s2 = pk2(a[i].z, a[i].z);
                fma2(acc[i][0], s2, wv0[2].x); fma2(acc[i][1], s2, wv0[2].y);
                fma2(acc[i][2], s2, wv1[2].x); fma2(acc[i][3], s2, wv1[2].y);
                const u64 s3 = pk2(a[i].w, a[i].w);
                fma2(acc[i][0], s3, wv0[3].x); fma2(acc[i][1], s3, wv0[3].y);
                fma2(acc[i][2], s3, wv1[3].x); fma2(acc[i][3], s3, wv1[3].y);
            }
        }
        // per-thread max over its 8 points, 8 cols
        float mx[8];
#pragma unroll
        for (int o = 0; o < 4; ++o) {
            float2 f = up2(acc[0][o]);
            float ma = f.x, mb = f.y;
#pragma unroll
            for (int i = 1; i < 8; ++i) {
                f = up2(acc[i][o]);
                ma = fmaxf(ma, f.x);
                mb = fmaxf(mb, f.y);
            }
            mx[2 * o]     = ma;
            mx[2 * o + 1] = mb;
        }
        *(float4*)&red[mg * 64 + ng * 8]     = make_float4(mx[0], mx[1], mx[2], mx[3]);
        *(float4*)&red[mg * 64 + ng * 8 + 4] = make_float4(mx[4], mx[5], mx[6], mx[7]);
        __syncthreads();
        if (t < 64) {
            float mv = red[t];
#pragma unroll
            for (int g = 1; g < 16; ++g) mv = fmaxf(mv, red[g * 64 + t]);
            feat_s[np * 64 + t] = mv + __ldg(b3 + np * 64 + t);
        }
        __syncthreads();
    }

    // ---- pt_out = feat @ oe_w + oe_b (100 outputs)
    if (t < EMB) {
        float acc = __ldg(oeb + t);
#pragma unroll 4
        for (int k = 0; k < 256; k += 4) {
            const float4 f = *(const float4*)&feat_s[k];
            acc = fmaf(f.x, __ldg(oew + (size_t)(k + 0) * EMB + t), acc);
            acc = fmaf(f.y, __ldg(oew + (size_t)(k + 1) * EMB + t), acc);
            acc = fmaf(f.z, __ldg(oew + (size_t)(k + 2) * EMB + t), acc);
            acc = fmaf(f.w, __ldg(oew + (size_t)(k + 3) * EMB + t), acc);
        }
        out[(size_t)n * OUTW + EMB + t] = acc;
    }
}

// ---------------------------------------------------------------------------
// Node branch (unchanged from the passing R2 version)
// ---------------------------------------------------------------------------
__global__ __launch_bounds__(256) void node_branch_kernel(
    const float* __restrict__ srcf,
    const float* __restrict__ reff,
    const void*  __restrict__ counts_raw,
    const float* __restrict__ w1,
    const float* __restrict__ b1,
    const float* __restrict__ w2,
    const float* __restrict__ b2,
    const float* __restrict__ sew,
    const float* __restrict__ seb,
    float* __restrict__ out)
{
    __shared__ float xs[8 * 260];
    __shared__ float hs[8 * 260];
    __shared__ int srow[8];
    __shared__ int sflag[8];

    const int t = threadIdx.x;
    const long long o0 = (long long)blockIdx.x * 8;

    if (t < 8) {
        const int* c32 = (const int*)counts_raw;
        const bool is64 = (c32[1] == 0 && c32[3] == 0);
        const long long o = o0 + t;
        long long cum = 0, ssum = 0, rsum = 0, idx = 0;
        int flag = 0;
        for (int b = 0; b < NB; ++b) {
            long long sc, rc;
            if (is64) {
                sc = ((const long long*)counts_raw)[2 * b];
                rc = ((const long long*)counts_raw)[2 * b + 1];
            } else {
                sc = c32[2 * b];
                rc = c32[2 * b + 1];
            }
            const long long tot = sc + rc;
            if (o < cum + tot) {
                const long long off = o - cum;
                if (off < sc) { flag = 0; idx = ssum + off; }
                else          { flag = 1; idx = rsum + (off - sc); }
                break;
            }
            cum += tot; ssum += sc; rsum += rc;
        }
        srow[t]  = (int)idx;
        sflag[t] = flag;
    }
    __syncthreads();

#pragma unroll
    for (int r = 0; r < 8; ++r) {
        const float* base = sflag[r] ? reff : srcf;
        xs[r * 260 + t] = base[(size_t)srow[r] * FEAT + t];
    }
    __syncthreads();

    float acc[8];

    {
        const float bv = __ldg(b1 + t);
#pragma unroll
        for (int r = 0; r < 8; ++r) acc[r] = bv;
#pragma unroll 1
        for (int k = 0; k < 256; k += 4) {
            const float w0 = __ldg(w1 + (size_t)(k + 0) * 256 + t);
            const float wq1 = __ldg(w1 + (size_t)(k + 1) * 256 + t);
            const float wq2 = __ldg(w1 + (size_t)(k + 2) * 256 + t);
            const float wq3 = __ldg(w1 + (size_t)(k + 3) * 256 + t);
#pragma unroll
            for (int r = 0; r < 8; ++r) {
                float4 xv = *(const float4*)&xs[r * 260 + k];
                acc[r] = fmaf(xv.x, w0, acc[r]);
                acc[r] = fmaf(xv.y, wq1, acc[r]);
                acc[r] = fmaf(xv.z, wq2, acc[r]);
                acc[r] = fmaf(xv.w, wq3, acc[r]);
            }
        }
#pragma unroll
        for (int r = 0; r < 8; ++r) hs[r * 260 + t] = fmaxf(acc[r], 0.0f);
    }
    __syncthreads();

    {
        const float bv = __ldg(b2 + t);
#pragma unroll
        for (int r = 0; r < 8; ++r) acc[r] = bv;
#pragma unroll 1
        for (int k = 0; k < 256; k += 4) {
            const float w0 = __ldg(w2 + (size_t)(k + 0) * 256 + t);
            const float wq1 = __ldg(w2 + (size_t)(k + 1) * 256 + t);
            const float wq2 = __ldg(w2 + (size_t)(k + 2) * 256 + t);
            const float wq3 = __ldg(w2 + (size_t)(k + 3) * 256 + t);
#pragma unroll
            for (int r = 0; r < 8; ++r) {
                float4 xv = *(const float4*)&hs[r * 260 + k];
                acc[r] = fmaf(xv.x, w0, acc[r]);
                acc[r] = fmaf(xv.y, wq1, acc[r]);
                acc[r] = fmaf(xv.z, wq2, acc[r]);
                acc[r] = fmaf(xv.w, wq3, acc[r]);
            }
        }
#pragma unroll
        for (int r = 0; r < 8; ++r) xs[r * 260 + t] = acc[r];
    }
    __syncthreads();

    if (t < EMB) {
        float accs[8];
        const float bv = __ldg(seb + t);
#pragma unroll
        for (int r = 0; r < 8; ++r) accs[r] = bv;
#pragma unroll 1
        for (int k = 0; k < 256; k += 4) {
            const float w0 = __ldg(sew + (size_t)(k + 0) * EMB + t);
            const float wq1 = __ldg(sew + (size_t)(k + 1) * EMB + t);
            const float wq2 = __ldg(sew + (size_t)(k + 2) * EMB + t);
            const float wq3 = __ldg(sew + (size_t)(k + 3) * EMB + t);
#pragma unroll
            for (int r = 0; r < 8; ++r) {
                float4 ev = *(const float4*)&xs[r * 260 + k];
                accs[r] = fmaf(ev.x, w0, accs[r]);
                accs[r] = fmaf(ev.y, wq1, accs[r]);
                accs[r] = fmaf(ev.z, wq2, accs[r]);
                accs[r] = fmaf(ev.w, wq3, accs[r]);
            }
        }
#pragma unroll
        for (int r = 0; r < 8; ++r)
            out[(size_t)(o0 + r) * OUTW + t] = accs[r];
    }
}

extern "C" void kernel_launch(void* const* d_in, const int* in_sizes, int n_in,
                              void* d_out, int out_size)
{
    const float* pts    = (const float*)d_in[0];
    const float* srcf   = (const float*)d_in[1];
    const float* reff   = (const float*)d_in[2];
    const void*  counts = d_in[3];
    const float* sg_w1  = (const float*)d_in[6];
    const float* sg_b1  = (const float*)d_in[7];
    const float* sg_w2  = (const float*)d_in[8];
    const float* sg_b2  = (const float*)d_in[9];
    const float* se_w   = (const float*)d_in[10];
    const float* se_b   = (const float*)d_in[11];
    const float* p_w1   = (const float*)d_in[12];
    const float* p_b1   = (const float*)d_in[13];
    const float* p_w2   = (const float*)d_in[14];
    const float* p_b2   = (const float*)d_in[15];
    const float* p_w3   = (const float*)d_in[16];
    const float* p_b3   = (const float*)d_in[17];
    const float* oe_w   = (const float*)d_in[18];
    const float* oe_b   = (const float*)d_in[19];
    float* out = (float*)d_out;

    cudaFuncSetAttribute(point_branch_kernel,
                         cudaFuncAttributeMaxDynamicSharedMemorySize, DSM_BYTES);

    node_branch_kernel<<<N_TOT / 8, 256>>>(srcf, reff, counts,
                                           sg_w1, sg_b1, sg_w2, sg_b2,
                                           se_w, se_b, out);
    point_branch_kernel<<<N_TOT, 128, DSM_BYTES>>>(pts, p_w1, p_b1, p_w2, p_b2,
                                                   p_w3, p_b3, oe_w, oe_b, out);
}

// round 4
// speedup vs baseline: 1.3561x; 1.3561x over previous
#include <cuda_runtime.h>

// Problem constants
#define NB    16
#define N_TOT 16384
#define PPT   128
#define FEAT  256
#define EMB   100
#define OUTW  200

typedef unsigned long long u64;

__device__ __forceinline__ u64 pk2(float lo, float hi) {
    u64 r; asm("mov.b64 %0, {%1,%2};" : "=l"(r) : "f"(lo), "f"(hi)); return r;
}
__device__ __forceinline__ void fma2(u64& a, u64 x, u64 w) {
    asm("fma.rn.f32x2 %0, %1, %2, %0;" : "+l"(a) : "l"(x), "l"(w));
}
__device__ __forceinline__ float2 up2(u64 v) {
    float2 f; asm("mov.b64 {%0,%1}, %2;" : "=f"(f.x), "=f"(f.y) : "l"(v)); return f;
}

// Bank-skewed row indexing: row stride 68/132 with +4 words per 8-row group so
// the 4 mg-groups in a warp hit distinct bank quads (8*132 = 1056 ≡ 0 mod 32).
#define H1I(p) ((p) * 68  + ((p) >> 3) * 4)
#define H2I(p) ((p) * 132 + ((p) >> 3) * 4)

// ---------------------------------------------------------------------------
// Point branch: block = one object, 128 threads, 4 groups of 32 points.
//   h1 = relu(pts @ W1 + b1)   (32x64 in shared)
//   h2 = relu(h1 @ W2 + b2)    (32x128 in shared)
//   h3 = h2 @ W3, max-pool accumulated in registers across groups
//   feat = max + b3 ; pt_out = feat @ oe_w + oe_b
// Column partitioning: layer2 warp w owns cols [w*32,w*32+32),
//                      layer3 warp w owns cols [w*64,w*64+64).
// Thread tile: 8 pts (mg=lane>>3) x 4 cols (L2) / 8 cols (L3), fma.rn.f32x2.
// ---------------------------------------------------------------------------
__global__ __launch_bounds__(128) void point_branch_kernel(
    const float* __restrict__ pts,   // (N_TOT, 128, 3)
    const float* __restrict__ w1,    // (3, 64)
    const float* __restrict__ b1,    // (64)
    const float* __restrict__ w2,    // (64, 128)
    const float* __restrict__ b2,    // (128)
    const float* __restrict__ w3,    // (128, 256)
    const float* __restrict__ b3,    // (256)
    const float* __restrict__ oew,   // (256, 100)
    const float* __restrict__ oeb,   // (100)
    float* __restrict__ out)         // (N_TOT, 200)
{
    __shared__ float h1s[2200];      // 32 x 64 skewed
    __shared__ float h2s[4240];      // 32 x 128 skewed
    __shared__ float feat_s[256];

    const int n    = blockIdx.x;
    const int t    = threadIdx.x;
    const int w    = t >> 5;         // warp id 0..3
    const int lane = t & 31;
    const int mg   = lane >> 3;      // 4 point groups of 8
    const int ng   = lane & 7;       // 8 column subtiles

    const int c2 = w * 32 + ng * 4;  // layer-2 col base (4 cols)
    const int c3 = w * 64 + ng * 8;  // layer-3 col base (8 cols)

    float runmax[8];
#pragma unroll
    for (int j = 0; j < 8; ++j) runmax[j] = -3.0e38f;

    const ulonglong2 b2v = __ldg((const ulonglong2*)(b2 + c2));

#pragma unroll 1
    for (int pg = 0; pg < 4; ++pg) {
        __syncthreads();  // prior-iteration h1/h2 readers done

        // ---- layer 1: 32 points; thread (pl, jq) computes 16 outputs
        {
            const int pl = t & 31;
            const int j0 = (t >> 5) * 16;
            const size_t pb = ((size_t)n * PPT + (size_t)pg * 32 + pl) * 3;
            const float x = pts[pb + 0];
            const float y = pts[pb + 1];
            const float z = pts[pb + 2];
            const int hb = H1I(pl);
#pragma unroll
            for (int j = 0; j < 16; j += 4) {
                const int jj = j0 + j;
                float4 v;
                v.x = fmaf(x, __ldg(w1 + jj + 0), fmaf(y, __ldg(w1 + 64 + jj + 0), fmaf(z, __ldg(w1 + 128 + jj + 0), __ldg(b1 + jj + 0))));
                v.y = fmaf(x, __ldg(w1 + jj + 1), fmaf(y, __ldg(w1 + 64 + jj + 1), fmaf(z, __ldg(w1 + 128 + jj + 1), __ldg(b1 + jj + 1))));
                v.z = fmaf(x, __ldg(w1 + jj + 2), fmaf(y, __ldg(w1 + 64 + jj + 2), fmaf(z, __ldg(w1 + 128 + jj + 2), __ldg(b1 + jj + 2))));
                v.w = fmaf(x, __ldg(w1 + jj + 3), fmaf(y, __ldg(w1 + 64 + jj + 3), fmaf(z, __ldg(w1 + 128 + jj + 3), __ldg(b1 + jj + 3))));
                v.x = fmaxf(v.x, 0.0f); v.y = fmaxf(v.y, 0.0f);
                v.z = fmaxf(v.z, 0.0f); v.w = fmaxf(v.w, 0.0f);
                *(float4*)&h1s[hb + jj] = v;
            }
        }
        __syncthreads();

        // ---- layer 2: thread tile 8 pts x 4 cols (cols c2..c2+4), f32x2
        {
            u64 acc[8][2];
#pragma unroll
            for (int i = 0; i < 8; ++i) { acc[i][0] = b2v.x; acc[i][1] = b2v.y; }
#pragma unroll 1
            for (int k = 0; k < 64; k += 4) {
                float4 a[8];
#pragma unroll
                for (int i = 0; i < 8; ++i)
                    a[i] = *(const float4*)&h1s[H1I(mg * 8 + i) + k];
                ulonglong2 wv[4];
#pragma unroll
                for (int q = 0; q < 4; ++q)
                    wv[q] = __ldg((const ulonglong2*)(w2 + (size_t)(k + q) * 128 + c2));
#pragma unroll
                for (int i = 0; i < 8; ++i) {
                    const u64 s0 = pk2(a[i].x, a[i].x);
                    fma2(acc[i][0], s0, wv[0].x); fma2(acc[i][1], s0, wv[0].y);
                    const u64 s1 = pk2(a[i].y, a[i].y);
                    fma2(acc[i][0], s1, wv[1].x); fma2(acc[i][1], s1, wv[1].y);
                    const u64 s2 = pk2(a[i].z, a[i].z);
                    fma2(acc[i][0], s2, wv[2].x); fma2(acc[i][1], s2, wv[2].y);
                    const u64 s3 = pk2(a[i].w, a[i].w);
                    fma2(acc[i][0], s3, wv[3].x); fma2(acc[i][1], s3, wv[3].y);
                }
            }
#pragma unroll
            for (int i = 0; i < 8; ++i) {
                const float2 p0 = up2(acc[i][0]), p1 = up2(acc[i][1]);
                float4 v;
                v.x = fmaxf(p0.x, 0.0f); v.y = fmaxf(p0.y, 0.0f);
                v.z = fmaxf(p1.x, 0.0f); v.w = fmaxf(p1.y, 0.0f);
                *(float4*)&h2s[H2I(mg * 8 + i) + c2] = v;
            }
        }
        __syncthreads();

        // ---- layer 3: thread tile 8 pts x 8 cols (cols c3..c3+8), f32x2,
        //      max folded into registers (cols fixed across pg).
        {
            u64 acc[8][4];
#pragma unroll
            for (int i = 0; i < 8; ++i) {
                acc[i][0] = 0ull; acc[i][1] = 0ull;
                acc[i][2] = 0ull; acc[i][3] = 0ull;
            }
#pragma unroll 1
            for (int k = 0; k < 128; k += 4) {
                float4 a[8];
#pragma unroll
                for (int i = 0; i < 8; ++i)
                    a[i] = *(const float4*)&h2s[H2I(mg * 8 + i) + k];
                ulonglong2 wv0[4], wv1[4];
#pragma unroll
                for (int q = 0; q < 4; ++q) {
                    const float* wr = w3 + (size_t)(k + q) * 256 + c3;
                    wv0[q] = __ldg((const ulonglong2*)(wr));
                    wv1[q] = __ldg((const ulonglong2*)(wr + 4));
                }
#pragma unroll
                for (int i = 0; i < 8; ++i) {
                    const u64 s0 = pk2(a[i].x, a[i].x);
                    fma2(acc[i][0], s0, wv0[0].x); fma2(acc[i][1], s0, wv0[0].y);
                    fma2(acc[i][2], s0, wv1[0].x); fma2(acc[i][3], s0, wv1[0].y);
                    const u64 s1 = pk2(a[i].y, a[i].y);
                    fma2(acc[i][0], s1, wv0[1].x); fma2(acc[i][1], s1, wv0[1].y);
                    fma2(acc[i][2], s1, wv1[1].x); fma2(acc[i][3], s1, wv1[1].y);
                    const u64 s2 = pk2(a[i].z, a[i].z);
                    fma2(acc[i][0], s2, wv0[2].x); fma2(acc[i][1], s2, wv0[2].y);
                    fma2(acc[i][2], s2, wv1[2].x); fma2(acc[i][3], s2, wv1[2].y);
                    const u64 s3 = pk2(a[i].w, a[i].w);
                    fma2(acc[i][0], s3, wv0[3].x); fma2(acc[i][1], s3, wv0[3].y);
                    fma2(acc[i][2], s3, wv1[3].x); fma2(acc[i][3], s3, wv1[3].y);
                }
            }
#pragma unroll
            for (int o = 0; o < 4; ++o) {
#pragma unroll
                for (int i = 0; i < 8; ++i) {
                    const float2 f = up2(acc[i][o]);
                    runmax[2 * o]     = fmaxf(runmax[2 * o],     f.x);
                    runmax[2 * o + 1] = fmaxf(runmax[2 * o + 1], f.y);
                }
            }
        }
    }

    // ---- reduce max across the 4 mg groups (same ng => same cols)
#pragma unroll
    for (int j = 0; j < 8; ++j) {
        float m = runmax[j];
        m = fmaxf(m, __shfl_xor_sync(0xffffffffu, m, 8));
        m = fmaxf(m, __shfl_xor_sync(0xffffffffu, m, 16));
        if (mg == 0) feat_s[c3 + j] = m + __ldg(b3 + c3 + j);
    }
    __syncthreads();

    // ---- pt_out = feat @ oe_w + oe_b (100 outputs)
    if (t < EMB) {
        float acc = __ldg(oeb + t);
#pragma unroll 4
        for (int k = 0; k < 256; k += 4) {
            const float4 f = *(const float4*)&feat_s[k];
            acc = fmaf(f.x, __ldg(oew + (size_t)(k + 0) * EMB + t), acc);
            acc = fmaf(f.y, __ldg(oew + (size_t)(k + 1) * EMB + t), acc);
            acc = fmaf(f.z, __ldg(oew + (size_t)(k + 2) * EMB + t), acc);
            acc = fmaf(f.w, __ldg(oew + (size_t)(k + 3) * EMB + t), acc);
        }
        out[(size_t)n * OUTW + EMB + t] = acc;
    }
}

// ---------------------------------------------------------------------------
// Node branch (unchanged, ~4% of runtime)
// ---------------------------------------------------------------------------
__global__ __launch_bounds__(256) void node_branch_kernel(
    const float* __restrict__ srcf,
    const float* __restrict__ reff,
    const void*  __restrict__ counts_raw,
    const float* __restrict__ w1,
    const float* __restrict__ b1,
    const float* __restrict__ w2,
    const float* __restrict__ b2,
    const float* __restrict__ sew,
    const float* __restrict__ seb,
    float* __restrict__ out)
{
    __shared__ float xs[8 * 260];
    __shared__ float hs[8 * 260];
    __shared__ int srow[8];
    __shared__ int sflag[8];

    const int t = threadIdx.x;
    const long long o0 = (long long)blockIdx.x * 8;

    if (t < 8) {
        const int* c32 = (const int*)counts_raw;
        const bool is64 = (c32[1] == 0 && c32[3] == 0);
        const long long o = o0 + t;
        long long cum = 0, ssum = 0, rsum = 0, idx = 0;
        int flag = 0;
        for (int b = 0; b < NB; ++b) {
            long long sc, rc;
            if (is64) {
                sc = ((const long long*)counts_raw)[2 * b];
                rc = ((const long long*)counts_raw)[2 * b + 1];
            } else {
                sc = c32[2 * b];
                rc = c32[2 * b + 1];
            }
            const long long tot = sc + rc;
            if (o < cum + tot) {
                const long long off = o - cum;
                if (off < sc) { flag = 0; idx = ssum + off; }
                else          { flag = 1; idx = rsum + (off - sc); }
                break;
            }
            cum += tot; ssum += sc; rsum += rc;
        }
        srow[t]  = (int)idx;
        sflag[t] = flag;
    }
    __syncthreads();

#pragma unroll
    for (int r = 0; r < 8; ++r) {
        const float* base = sflag[r] ? reff : srcf;
        xs[r * 260 + t] = base[(size_t)srow[r] * FEAT + t];
    }
    __syncthreads();

    float acc[8];

    {
        const float bv = __ldg(b1 + t);
#pragma unroll
        for (int r = 0; r < 8; ++r) acc[r] = bv;
#pragma unroll 1
        for (int k = 0; k < 256; k += 4) {
            const float w0 = __ldg(w1 + (size_t)(k + 0) * 256 + t);
            const float wq1 = __ldg(w1 + (size_t)(k + 1) * 256 + t);
            const float wq2 = __ldg(w1 + (size_t)(k + 2) * 256 + t);
            const float wq3 = __ldg(w1 + (size_t)(k + 3) * 256 + t);
#pragma unroll
            for (int r = 0; r < 8; ++r) {
                float4 xv = *(const float4*)&xs[r * 260 + k];
                acc[r] = fmaf(xv.x, w0, acc[r]);
                acc[r] = fmaf(xv.y, wq1, acc[r]);
                acc[r] = fmaf(xv.z, wq2, acc[r]);
                acc[r] = fmaf(xv.w, wq3, acc[r]);
            }
        }
#pragma unroll
        for (int r = 0; r < 8; ++r) hs[r * 260 + t] = fmaxf(acc[r], 0.0f);
    }
    __syncthreads();

    {
        const float bv = __ldg(b2 + t);
#pragma unroll
        for (int r = 0; r < 8; ++r) acc[r] = bv;
#pragma unroll 1
        for (int k = 0; k < 256; k += 4) {
            const float w0 = __ldg(w2 + (size_t)(k + 0) * 256 + t);
            const float wq1 = __ldg(w2 + (size_t)(k + 1) * 256 + t);
            const float wq2 = __ldg(w2 + (size_t)(k + 2) * 256 + t);
            const float wq3 = __ldg(w2 + (size_t)(k + 3) * 256 + t);
#pragma unroll
            for (int r = 0; r < 8; ++r) {
                float4 xv = *(const float4*)&hs[r * 260 + k];
                acc[r] = fmaf(xv.x, w0, acc[r]);
                acc[r] = fmaf(xv.y, wq1, acc[r]);
                acc[r] = fmaf(xv.z, wq2, acc[r]);
                acc[r] = fmaf(xv.w, wq3, acc[r]);
            }
        }
#pragma unroll
        for (int r = 0; r < 8; ++r) xs[r * 260 + t] = acc[r];
    }
    __syncthreads();

    if (t < EMB) {
        float accs[8];
        const float bv = __ldg(seb + t);
#pragma unroll
        for (int r = 0; r < 8; ++r) accs[r] = bv;
#pragma unroll 1
        for (int k = 0; k < 256; k += 4) {
            const float w0 = __ldg(sew + (size_t)(k + 0) * EMB + t);
            const float wq1 = __ldg(sew + (size_t)(k + 1) * EMB + t);
            const float wq2 = __ldg(sew + (size_t)(k + 2) * EMB + t);
            const float wq3 = __ldg(sew + (size_t)(k + 3) * EMB + t);
#pragma unroll
            for (int r = 0; r < 8; ++r) {
                float4 ev = *(const float4*)&xs[r * 260 + k];
                accs[r] = fmaf(ev.x, w0, accs[r]);
                accs[r] = fmaf(ev.y, wq1, accs[r]);
                accs[r] = fmaf(ev.z, wq2, accs[r]);
                accs[r] = fmaf(ev.w, wq3, accs[r]);
            }
        }
#pragma unroll
        for (int r = 0; r < 8; ++r)
            out[(size_t)(o0 + r) * OUTW + t] = accs[r];
    }
}

extern "C" void kernel_launch(void* const* d_in, const int* in_sizes, int n_in,
                              void* d_out, int out_size)
{
    const float* pts    = (const float*)d_in[0];
    const float* srcf   = (const float*)d_in[1];
    const float* reff   = (const float*)d_in[2];
    const void*  counts = d_in[3];
    const float* sg_w1  = (const float*)d_in[6];
    const float* sg_b1  = (const float*)d_in[7];
    const float* sg_w2  = (const float*)d_in[8];
    const float* sg_b2  = (const float*)d_in[9];
    const float* se_w   = (const float*)d_in[10];
    const float* se_b   = (const float*)d_in[11];
    const float* p_w1   = (const float*)d_in[12];
    const float* p_b1   = (const float*)d_in[13];
    const float* p_w2   = (const float*)d_in[14];
    const float* p_b2   = (const float*)d_in[15];
    const float* p_w3   = (const float*)d_in[16];
    const float* p_b3   = (const float*)d_in[17];
    const float* oe_w   = (const float*)d_in[18];
    const float* oe_b   = (const float*)d_in[19];
    float* out = (float*)d_out;

    node_branch_kernel<<<N_TOT / 8, 256>>>(srcf, reff, counts,
                                           sg_w1, sg_b1, sg_w2, sg_b2,
                                           se_w, se_b, out);
    point_branch_kernel<<<N_TOT, 128>>>(pts, p_w1, p_b1, p_w2, p_b2,
                                        p_w3, p_b3, oe_w, oe_b, out);
}